// round 17
// baseline (speedup 1.0000x reference)
#include <cuda_runtime.h>
#include <cstdint>

// Transducer KD loss prep — persistent block-cooperative cp.async slabs.
// logits/teacher (N=8,T=200,U=50,V=500) fp32; y (N,U) i32; x_lens,y_lens (N,) i32.
// Output (2, N, T, U, 3) fp32.
//
// Block (128 thr, 4 warps) processes a QUAD of 4 consecutive positions per
// iteration. The 4 student rows are CONTIGUOUS 8000B in gmem (ditto teacher):
// the whole block cooperatively cp.asyncs the 16KB slab into a 2-stage smem
// ring (32KB). In-flight bytes live in the LSU, not the regfile: 7 blocks/SM
// x 16KB = 112KB/SM, breaking the 64KB register-resident plateau of R2-R16.
// Per-warp compute from smem (gather = direct smem read; regs stay ~40).

#define TN 8
#define TT 200
#define TU 50
#define TV 500
#define ROWS (TN * TT * TU)     // 80000
#define QUADS (ROWS / 4)        // 20000
#define T_EPS 1e-10f
#define NEG_BIG -1e30f

#define THREADS 128
#define NBLOCKS (148 * 7)       // 1036 persistent blocks
// stage = 4 positions x (student row + teacher row) = 1000 x 16B chunks
#define STAGE_CHUNKS 1000       // 16000 B
#define ROW_CHUNKS 125          // 2000 B per row

__device__ __forceinline__ void cp16(uint32_t smem_addr, const float* gptr) {
    asm volatile("cp.async.cg.shared.global [%0], [%1], 16;\n"
                 :: "r"(smem_addr), "l"(gptr));
}

__global__ void __launch_bounds__(THREADS)
transducer_kd_kernel(const float* __restrict__ logits,
                     const float* __restrict__ teacher,
                     const int*   __restrict__ y,
                     const int*   __restrict__ x_lens,
                     const int*   __restrict__ y_lens,
                     float*       __restrict__ out)
{
    __shared__ __align__(16) float4 buf[2][STAGE_CHUNKS];   // 32000 B

    const int tid  = threadIdx.x;
    const int w    = tid >> 5;
    const int lane = tid & 31;
    const bool tail = (lane < 29);        // 125 float4 per row

    // active-mask for the 4 positions of quad q
    auto act_mask = [&](int q) -> int {
        int m = 0;
        #pragma unroll
        for (int i = 0; i < 4; i++) {
            const int r  = q * 4 + i;
            const int n  = r / (TT * TU);
            const int tu = r - n * (TT * TU);
            const int t  = tu / TU;
            const int u  = tu - t * TU;
            if (t < __ldg(x_lens + n) && u < __ldg(y_lens + n)) m |= 1 << i;
        }
        return m;
    };

    // cooperative copy of quad q's 16KB slab into stage st
    auto issue = [&](int q, int st, int m) {
        const float* sg = logits  + (size_t)q * 4 * TV;   // 8000B contiguous
        const float* tg = teacher + (size_t)q * 4 * TV;
        uint32_t sb = (uint32_t)__cvta_generic_to_shared(&buf[st][0]);
        #pragma unroll
        for (int k = 0; k < 8; k++) {
            const int chunk = tid + k * THREADS;          // 0..1023
            if (chunk < STAGE_CHUNKS) {
                const int isT   = chunk >= 500;
                const int local = chunk - (isT ? 500 : 0);  // 0..499
                const int pos   = local / ROW_CHUNKS;       // 0..3
                if (m & (1 << pos)) {
                    const float* g = (isT ? tg : sg) + local * 4;
                    cp16(sb + chunk * 16, g);
                }
            }
        }
    };

    // per-warp compute of position w of quad q from stage st
    auto compute = [&](int q, int st, int m) {
        const int r = q * 4 + w;
        float* os = out + (size_t)r * 3;
        float* ot = out + (size_t)(ROWS + r) * 3;
        if (!((m >> w) & 1)) {
            if (lane < 3) { os[lane] = 0.0f; ot[lane] = 0.0f; }
            return;
        }
        const float*  sbuf = (const float*)&buf[st][w * ROW_CHUNKS];
        const float*  tbuf = (const float*)&buf[st][500 + w * ROW_CHUNKS];
        const float4* s4 = (const float4*)sbuf;
        const float4* t4 = (const float4*)tbuf;

        float4 sv0 = s4[lane];
        float4 sv1 = s4[lane + 32];
        float4 sv2 = s4[lane + 64];
        float4 tv0 = t4[lane];
        float4 tv1 = t4[lane + 32];
        float4 tv2 = t4[lane + 64];
        float4 sv3 = make_float4(NEG_BIG, NEG_BIG, NEG_BIG, NEG_BIG);
        float4 tv3 = make_float4(NEG_BIG, NEG_BIG, NEG_BIG, NEG_BIG);
        if (tail) { sv3 = s4[lane + 96]; tv3 = t4[lane + 96]; }

        float sa = (__expf(sv0.x) + __expf(sv0.y)) + (__expf(sv0.z) + __expf(sv0.w));
        sa += (__expf(sv1.x) + __expf(sv1.y)) + (__expf(sv1.z) + __expf(sv1.w));
        sa += (__expf(sv2.x) + __expf(sv2.y)) + (__expf(sv2.z) + __expf(sv2.w));
        sa += (__expf(sv3.x) + __expf(sv3.y)) + (__expf(sv3.z) + __expf(sv3.w));
        float ta = (__expf(tv0.x) + __expf(tv0.y)) + (__expf(tv0.z) + __expf(tv0.w));
        ta += (__expf(tv1.x) + __expf(tv1.y)) + (__expf(tv1.z) + __expf(tv1.w));
        ta += (__expf(tv2.x) + __expf(tv2.y)) + (__expf(tv2.z) + __expf(tv2.w));
        ta += (__expf(tv3.x) + __expf(tv3.y)) + (__expf(tv3.z) + __expf(tv3.w));

        #pragma unroll
        for (int off = 16; off > 0; off >>= 1) {
            sa += __shfl_xor_sync(0xFFFFFFFFu, sa, off);
            ta += __shfl_xor_sync(0xFFFFFFFFu, ta, off);
        }

        if (lane == 0) {
            const int n  = r / (TT * TU);
            const int tu = r - n * (TT * TU);
            const int u  = tu - (tu / TU) * TU;
            const int yi = __ldg(y + n * TU + u);
            const float s_ly = sbuf[yi];      // direct smem gather
            const float t_ly = tbuf[yi];
            const float s_lb = sbuf[0];
            const float t_lb = tbuf[0];

            const float sinv   = __fdividef(1.0f, sa);
            const float spy    = __expf(s_ly) * sinv;
            const float sblank = __expf(s_lb) * sinv;
            const float srem   = 1.0f - spy - sblank;
            os[0] = __logf(fminf(fmaxf(spy,    T_EPS), 1.0f));
            os[1] = __logf(fminf(fmaxf(sblank, T_EPS), 1.0f));
            os[2] = __logf(fminf(fmaxf(srem,   T_EPS), 1.0f));

            const float tinv   = __fdividef(1.0f, ta);
            const float tpy    = __expf(t_ly) * tinv;
            const float tblank = __expf(t_lb) * tinv;
            const float trem   = 1.0f - tpy - tblank;
            ot[0] = tpy;
            ot[1] = tblank;
            ot[2] = (trem < 0.0f) ? T_EPS : trem;
        }
    };

    // ---- persistent double-buffered main loop ----
    int q = blockIdx.x;
    if (q >= QUADS) return;

    int m_cur = act_mask(q);
    issue(q, 0, m_cur);
    asm volatile("cp.async.commit_group;\n" ::: "memory");

    int stage = 0;
    while (q < QUADS) {
        const int qn = q + NBLOCKS;
        int m_nxt = 0;
        if (qn < QUADS) {
            m_nxt = act_mask(qn);
            issue(qn, stage ^ 1, m_nxt);
        }
        asm volatile("cp.async.commit_group;\n" ::: "memory");
        asm volatile("cp.async.wait_group 1;\n" ::: "memory");
        __syncthreads();                       // slab visible to all warps

        compute(q, stage, m_cur);

        __syncthreads();                       // release buffer before reuse
        q = qn;
        m_cur = m_nxt;
        stage ^= 1;
    }
}

extern "C" void kernel_launch(void* const* d_in, const int* in_sizes, int n_in,
                              void* d_out, int out_size)
{
    const float* logits  = (const float*)d_in[0];
    const float* teacher = (const float*)d_in[1];
    const int*   y       = (const int*)d_in[2];
    const int*   x_lens  = (const int*)d_in[3];
    const int*   y_lens  = (const int*)d_in[4];
    float* out = (float*)d_out;

    transducer_kd_kernel<<<NBLOCKS, THREADS>>>(
        logits, teacher, y, x_lens, y_lens, out);
}